// round 16
// baseline (speedup 1.0000x reference)
#include <cuda_runtime.h>
#include <cuda_fp16.h>
#include <cstdint>

// UVLearner, fp16 mma.sync. R15 -> R16:
//  - software pipeline: epilogue(t-1) interleaved with MMA(t) via two cA
//    register buffers (no barrier between them; scheduler overlaps
//    HMMA with ex2/FFMA2)
//  - A fragments reloaded per tile (16 LDSM4) to free registers
// 8 warps (4 q-groups x 2 k-groups), each 32q x 64k per tile.

#define XROW 272               // 256B row + 16B pad -> conflict-free LDSM
#define SM_X  0u
#define SM_Y  34816u           // 3 buffers x 34816
#define SM_RED 139264u         // 2*128*3 floats
#define SMEM_TOTAL 142336u

__device__ uint4 g_y[4][4096][16];   // y fp16 [b][key][c/8] half2 x8

__device__ __forceinline__ float ex2(float a) {
    float r; asm("ex2.approx.f32 %0, %1;" : "=f"(r) : "f"(a)); return r;
}
__device__ __forceinline__ unsigned long long pk2(float lo, float hi) {
    unsigned long long r;
    asm("mov.b64 %0, {%1, %2};" : "=l"(r) : "f"(lo), "f"(hi));
    return r;
}
__device__ __forceinline__ void upk2(float& lo, float& hi, unsigned long long v) {
    asm("mov.b64 {%0, %1}, %2;" : "=f"(lo), "=f"(hi) : "l"(v));
}
__device__ __forceinline__ unsigned long long ffma2(unsigned long long a,
                                                    unsigned long long b,
                                                    unsigned long long c) {
    unsigned long long d;
    asm("fma.rn.f32x2 %0, %1, %2, %3;" : "=l"(d) : "l"(a), "l"(b), "l"(c));
    return d;
}
#define LDSM4(r, a) \
    asm volatile("ldmatrix.sync.aligned.m8n8.x4.shared.b16 {%0,%1,%2,%3}, [%4];" \
        : "=r"((r)[0]), "=r"((r)[1]), "=r"((r)[2]), "=r"((r)[3]) : "r"(a))

__device__ __forceinline__ void mma16816(float* c, const uint32_t* a,
                                         const uint32_t* b) {
    asm volatile(
        "mma.sync.aligned.m16n8k16.row.col.f32.f16.f16.f32 "
        "{%0,%1,%2,%3}, {%4,%5,%6,%7}, {%8,%9}, {%0,%1,%2,%3};"
        : "+f"(c[0]), "+f"(c[1]), "+f"(c[2]), "+f"(c[3])
        : "r"(a[0]), "r"(a[1]), "r"(a[2]), "r"(a[3]), "r"(b[0]), "r"(b[1]));
}
__device__ __forceinline__ uint32_t pkh(float v0, float v1) {
    __half h0 = __float2half_rn(v0), h1 = __float2half_rn(v1);
    return ((uint32_t)__half_as_ushort(h1) << 16) | __half_as_ushort(h0);
}

// ---------- pre-pass: y -> [b][k][c] fp16 ----------
__global__ __launch_bounds__(256)
void ytrans_kernel(const float* __restrict__ y) {
    int i = blockIdx.x * 256 + threadIdx.x;   // 4 * 16 * 4096
    int k  = i & 4095;
    int cg = (i >> 12) & 15;
    int b  = i >> 16;
    const float* src = y + ((size_t)(b * 128 + cg * 8)) * 4096 + k;
    uint32_t h[4];
    #pragma unroll
    for (int j = 0; j < 4; j++)
        h[j] = pkh(src[(size_t)(2 * j) * 4096], src[(size_t)(2 * j + 1) * 4096]);
    g_y[b][k][cg] = make_uint4(h[0], h[1], h[2], h[3]);
}

// ---------- main kernel ----------
__global__ __launch_bounds__(256, 1)
void uv_kernel(const float* __restrict__ x, float* __restrict__ out) {
    extern __shared__ char smem[];
    const uint32_t sb = (uint32_t)__cvta_generic_to_shared(smem);
    const int tid = threadIdx.x, wid = tid >> 5, lane = tid & 31;
    const int bb = blockIdx.x >> 5, q0 = (blockIdx.x & 31) * 128;
    const float* xb = x + (size_t)bb * 128 * 4096 + q0;
    const float K2E = 0.12754245778362382f;   // log2(e)/sqrt(128)

    auto prefetch = [&](int t) {
        uint32_t dst0 = sb + SM_Y + (uint32_t)(t % 3) * 34816u;
        #pragma unroll
        for (int i = tid; i < 2048; i += 256) {
            int r = i >> 4, j = i & 15;
            uint32_t d = dst0 + (uint32_t)(r * XROW + j * 16);
            const uint4* s = &g_y[bb][t * 128 + r][j];
            asm volatile("cp.async.ca.shared.global [%0], [%1], 16;"
                         :: "r"(d), "l"(s));
        }
    };

    prefetch(0);
    asm volatile("cp.async.commit_group;");
    prefetch(1);
    asm volatile("cp.async.commit_group;");

    // x prologue: scale + fp16, store [q][c] rows
    for (int i = tid; i < 8192; i += 256) {
        int c = (i >> 7) * 2, q = i & 127;
        float v0 = xb[(size_t)c * 4096 + q] * K2E;
        float v1 = xb[(size_t)(c + 1) * 4096 + q] * K2E;
        *(uint32_t*)(smem + SM_X + q * XROW + c * 2) = pkh(v0, v1);
    }
    __syncthreads();

    // warp tiling: 8 warps = 4 q-groups x 2 k-groups; 32q x 64k per warp
    const int mq = (wid & 3) * 32;
    const int nw = wid >> 2;          // 0..1
    const int nb = nw * 64;
    const uint32_t aB = sb + SM_X
        + (uint32_t)((mq + (lane & 15)) * XROW + (lane >> 4) * 16);
    const uint32_t bOff = (uint32_t)((nb + (lane >> 4) * 8 + (lane & 7)) * XROW
                                     + ((lane >> 3) & 1) * 16);

    unsigned long long den2[4], n02[4], n12[4], col2[8];
    const unsigned long long one2 = pk2(1.0f, 1.0f);
    #pragma unroll
    for (int a = 0; a < 4; a++) { den2[a] = 0ull; n02[a] = 0ull; n12[a] = 0ull; }
    #pragma unroll
    for (int j = 0; j < 8; j++) {
        float c0 = (float)(j * 8 + 2 * (lane & 3)) + 0.5f;   // nb mod 64 drops out
        col2[j] = pk2(c0, c0 + 1.0f);
    }

    float cA0[2][8][4], cA1[2][8][4];

    // MMA for one tile into buffer c
    auto do_mma = [&](float (*c)[8][4], int t) {
        const uint32_t bB = sb + SM_Y + (uint32_t)(t % 3) * 34816u + bOff;
        #pragma unroll
        for (int m = 0; m < 2; m++)
            #pragma unroll
            for (int j = 0; j < 8; j++)
                #pragma unroll
                for (int e = 0; e < 4; e++) c[m][j][e] = 0.f;
        #pragma unroll
        for (int ks = 0; ks < 8; ks++) {
            uint32_t ah0[4], ah1[4], bf[4][4];
            LDSM4(ah0, aB + ks * 32);
            LDSM4(ah1, aB + ks * 32 + 16 * XROW);
            LDSM4(bf[0], bB + ks * 32);
            LDSM4(bf[1], bB + ks * 32 + 16 * XROW);
            LDSM4(bf[2], bB + ks * 32 + 32 * XROW);
            LDSM4(bf[3], bB + ks * 32 + 48 * XROW);
            #pragma unroll
            for (int jb = 0; jb < 4; jb++) {
                mma16816(c[0][2 * jb],     ah0, bf[jb]);
                mma16816(c[0][2 * jb + 1], ah0, bf[jb] + 2);
                mma16816(c[1][2 * jb],     ah1, bf[jb]);
                mma16816(c[1][2 * jb + 1], ah1, bf[jb] + 2);
            }
        }
    };

    // softmax epilogue for one tile's fragments (registers only)
    auto epi = [&](float (*c)[8][4], int t) {
        const float rowc = (float)(2 * t + nw) + 0.5f;
        const unsigned long long row2 = pk2(rowc, rowc);
        #pragma unroll
        for (int m = 0; m < 2; m++)
            #pragma unroll
            for (int h = 0; h < 2; h++) {
                int a = m * 2 + h;
                #pragma unroll
                for (int j = 0; j < 8; j++) {
                    unsigned long long e2 =
                        pk2(ex2(c[m][j][2 * h]), ex2(c[m][j][2 * h + 1]));
                    den2[a] = ffma2(e2, one2,    den2[a]);
                    n02[a]  = ffma2(e2, col2[j], n02[a]);
                    n12[a]  = ffma2(e2, row2,    n12[a]);
                }
            }
    };

    // tile 0
    asm volatile("cp.async.wait_group 1;" ::: "memory");
    __syncthreads();
    prefetch(2);
    asm volatile("cp.async.commit_group;");
    do_mma(cA0, 0);

    // tiles 1..31: MMA(t) overlapped with epilogue(t-1)
    for (int t = 1; t < 32; t++) {
        if (t < 31) asm volatile("cp.async.wait_group 1;" ::: "memory");
        else        asm volatile("cp.async.wait_group 0;" ::: "memory");
        __syncthreads();
        if (t + 2 < 32) {
            prefetch(t + 2);
            asm volatile("cp.async.commit_group;");
        }
        if (t & 1) { do_mma(cA1, t); epi(cA0, t - 1); }
        else       { do_mma(cA0, t); epi(cA1, t - 1); }
    }
    epi(cA1, 31);   // t=31 is odd -> cA1

    // fold packed halves, reduce across the 4 lanes of each row group
    float* red = (float*)(smem + SM_RED);
    #pragma unroll
    for (int a = 0; a < 4; a++) {
        float dl, dh, al, ah2, bl, bh;
        upk2(dl, dh, den2[a]);
        upk2(al, ah2, n02[a]);
        upk2(bl, bh, n12[a]);
        float den = dl + dh, n0 = al + ah2, n1 = bl + bh;
        #pragma unroll
        for (int off = 1; off < 4; off <<= 1) {
            den += __shfl_xor_sync(0xffffffffu, den, off, 4);
            n0  += __shfl_xor_sync(0xffffffffu, n0,  off, 4);
            n1  += __shfl_xor_sync(0xffffffffu, n1,  off, 4);
        }
        if ((lane & 3) == 0) {
            int qrow = mq + (a >> 1) * 16 + (lane >> 2) + (a & 1) * 8;
            int base = (nw * 128 + qrow) * 3;
            red[base] = den; red[base + 1] = n0; red[base + 2] = n1;
        }
    }
    __syncthreads();

    if (tid < 128) {
        float d  = red[tid * 3]     + red[(128 + tid) * 3];
        float n0 = red[tid * 3 + 1] + red[(128 + tid) * 3 + 1];
        float n1 = red[tid * 3 + 2] + red[(128 + tid) * 3 + 2];
        float inv = 1.0f / (32.0f * d);   // (uv/64)*2 - 1
        float* o = out + ((size_t)bb * 4096 + q0 + tid) * 2;
        o[0] = n0 * inv - 1.0f;
        o[1] = n1 * inv - 1.0f;
    }
}

extern "C" void kernel_launch(void* const* d_in, const int* in_sizes, int n_in,
                              void* d_out, int out_size) {
    const float* x = (const float*)d_in[0];
    const float* y = (const float*)d_in[1];
    float* out = (float*)d_out;

    cudaFuncSetAttribute(uv_kernel,
                         cudaFuncAttributeMaxDynamicSharedMemorySize,
                         (int)SMEM_TOTAL);
    ytrans_kernel<<<1024, 256>>>(y);
    uv_kernel<<<128, 256, SMEM_TOTAL>>>(x, out);
}

// round 17
// speedup vs baseline: 1.0202x; 1.0202x over previous
#include <cuda_runtime.h>
#include <cuda_fp16.h>
#include <cstdint>

// UVLearner, fp16 mma.sync. R16 -> R17:
//  - revert R16's register double-buffer (it spilled: 250 regs, L1/alu up)
//  - R15 structure (persistent A frags, single cA buffer, 3-deep Y ring,
//    1 sync/tile) + WARP-ROLE STAGGERING:
//      even warps: MMA(t) then epilogue(t)
//      odd  warps: epilogue(t-1) then MMA(t)
//    -> per SMSP, tensor (even warp) and MUFU/FMA (odd warp) overlap
//    every iteration at zero register cost.

#define XROW 272               // 256B row + 16B pad -> conflict-free LDSM
#define SM_X  0u
#define SM_Y  34816u           // 3 buffers x 34816
#define SM_RED 139264u         // 2*128*3 floats
#define SMEM_TOTAL 142336u

__device__ uint4 g_y[4][4096][16];   // y fp16 [b][key][c/8] half2 x8

__device__ __forceinline__ float ex2(float a) {
    float r; asm("ex2.approx.f32 %0, %1;" : "=f"(r) : "f"(a)); return r;
}
__device__ __forceinline__ unsigned long long pk2(float lo, float hi) {
    unsigned long long r;
    asm("mov.b64 %0, {%1, %2};" : "=l"(r) : "f"(lo), "f"(hi));
    return r;
}
__device__ __forceinline__ void upk2(float& lo, float& hi, unsigned long long v) {
    asm("mov.b64 {%0, %1}, %2;" : "=f"(lo), "=f"(hi) : "l"(v));
}
__device__ __forceinline__ unsigned long long ffma2(unsigned long long a,
                                                    unsigned long long b,
                                                    unsigned long long c) {
    unsigned long long d;
    asm("fma.rn.f32x2 %0, %1, %2, %3;" : "=l"(d) : "l"(a), "l"(b), "l"(c));
    return d;
}
#define LDSM4(r, a) \
    asm volatile("ldmatrix.sync.aligned.m8n8.x4.shared.b16 {%0,%1,%2,%3}, [%4];" \
        : "=r"((r)[0]), "=r"((r)[1]), "=r"((r)[2]), "=r"((r)[3]) : "r"(a))

__device__ __forceinline__ void mma16816(float* c, const uint32_t* a,
                                         const uint32_t* b) {
    asm volatile(
        "mma.sync.aligned.m16n8k16.row.col.f32.f16.f16.f32 "
        "{%0,%1,%2,%3}, {%4,%5,%6,%7}, {%8,%9}, {%0,%1,%2,%3};"
        : "+f"(c[0]), "+f"(c[1]), "+f"(c[2]), "+f"(c[3])
        : "r"(a[0]), "r"(a[1]), "r"(a[2]), "r"(a[3]), "r"(b[0]), "r"(b[1]));
}
__device__ __forceinline__ uint32_t pkh(float v0, float v1) {
    __half h0 = __float2half_rn(v0), h1 = __float2half_rn(v1);
    return ((uint32_t)__half_as_ushort(h1) << 16) | __half_as_ushort(h0);
}

// ---------- pre-pass: y -> [b][k][c] fp16 ----------
__global__ __launch_bounds__(256)
void ytrans_kernel(const float* __restrict__ y) {
    int i = blockIdx.x * 256 + threadIdx.x;   // 4 * 16 * 4096
    int k  = i & 4095;
    int cg = (i >> 12) & 15;
    int b  = i >> 16;
    const float* src = y + ((size_t)(b * 128 + cg * 8)) * 4096 + k;
    uint32_t h[4];
    #pragma unroll
    for (int j = 0; j < 4; j++)
        h[j] = pkh(src[(size_t)(2 * j) * 4096], src[(size_t)(2 * j + 1) * 4096]);
    g_y[b][k][cg] = make_uint4(h[0], h[1], h[2], h[3]);
}

// ---------- main kernel ----------
__global__ __launch_bounds__(256, 1)
void uv_kernel(const float* __restrict__ x, float* __restrict__ out) {
    extern __shared__ char smem[];
    const uint32_t sb = (uint32_t)__cvta_generic_to_shared(smem);
    const int tid = threadIdx.x, wid = tid >> 5, lane = tid & 31;
    const int bb = blockIdx.x >> 5, q0 = (blockIdx.x & 31) * 128;
    const float* xb = x + (size_t)bb * 128 * 4096 + q0;
    const float K2E = 0.12754245778362382f;   // log2(e)/sqrt(128)

    auto prefetch = [&](int t) {
        uint32_t dst0 = sb + SM_Y + (uint32_t)(t % 3) * 34816u;
        #pragma unroll
        for (int i = tid; i < 2048; i += 256) {
            int r = i >> 4, j = i & 15;
            uint32_t d = dst0 + (uint32_t)(r * XROW + j * 16);
            const uint4* s = &g_y[bb][t * 128 + r][j];
            asm volatile("cp.async.ca.shared.global [%0], [%1], 16;"
                         :: "r"(d), "l"(s));
        }
    };

    prefetch(0);
    asm volatile("cp.async.commit_group;");
    prefetch(1);
    asm volatile("cp.async.commit_group;");

    // x prologue: scale + fp16, store [q][c] rows
    for (int i = tid; i < 8192; i += 256) {
        int c = (i >> 7) * 2, q = i & 127;
        float v0 = xb[(size_t)c * 4096 + q] * K2E;
        float v1 = xb[(size_t)(c + 1) * 4096 + q] * K2E;
        *(uint32_t*)(smem + SM_X + q * XROW + c * 2) = pkh(v0, v1);
    }
    __syncthreads();

    // warp tiling: 8 warps = 4 q-groups x 2 k-groups; 32q x 64k per warp
    const int mq = (wid & 3) * 32;
    const int nw = wid >> 2;          // 0..1
    const int nb = nw * 64;
    const int late = wid & 1;         // odd warps defer epilogue half a step
    const uint32_t aB = sb + SM_X
        + (uint32_t)((mq + (lane & 15)) * XROW + (lane >> 4) * 16);
    const uint32_t bOff = (uint32_t)((nb + (lane >> 4) * 8 + (lane & 7)) * XROW
                                     + ((lane >> 3) & 1) * 16);

    // persistent A fragments: 32q x 128c, loaded once (64 regs)
    uint32_t ah[8][2][4];
    #pragma unroll
    for (int ks = 0; ks < 8; ks++) {
        LDSM4(ah[ks][0], aB + ks * 32);
        LDSM4(ah[ks][1], aB + ks * 32 + 16 * XROW);
    }

    unsigned long long den2[4], n02[4], n12[4], col2[8];
    const unsigned long long one2 = pk2(1.0f, 1.0f);
    #pragma unroll
    for (int a = 0; a < 4; a++) { den2[a] = 0ull; n02[a] = 0ull; n12[a] = 0ull; }
    #pragma unroll
    for (int j = 0; j < 8; j++) {
        float c0 = (float)(j * 8 + 2 * (lane & 3)) + 0.5f;   // nb mod 64 drops out
        col2[j] = pk2(c0, c0 + 1.0f);
    }

    float cA[2][8][4];

    auto do_mma = [&](int t) {
        const uint32_t bB = sb + SM_Y + (uint32_t)(t % 3) * 34816u + bOff;
        #pragma unroll
        for (int m = 0; m < 2; m++)
            #pragma unroll
            for (int j = 0; j < 8; j++)
                #pragma unroll
                for (int e = 0; e < 4; e++) cA[m][j][e] = 0.f;
        #pragma unroll
        for (int ks = 0; ks < 8; ks++) {
            uint32_t bf[4][4];
            LDSM4(bf[0], bB + ks * 32);
            LDSM4(bf[1], bB + ks * 32 + 16 * XROW);
            LDSM4(bf[2], bB + ks * 32 + 32 * XROW);
            LDSM4(bf[3], bB + ks * 32 + 48 * XROW);
            #pragma unroll
            for (int jb = 0; jb < 4; jb++) {
                mma16816(cA[0][2 * jb],     ah[ks][0], bf[jb]);
                mma16816(cA[0][2 * jb + 1], ah[ks][0], bf[jb] + 2);
                mma16816(cA[1][2 * jb],     ah[ks][1], bf[jb]);
                mma16816(cA[1][2 * jb + 1], ah[ks][1], bf[jb] + 2);
            }
        }
    };

    auto epi = [&](int t) {
        const float rowc = (float)(2 * t + nw) + 0.5f;
        const unsigned long long row2 = pk2(rowc, rowc);
        #pragma unroll
        for (int m = 0; m < 2; m++)
            #pragma unroll
            for (int h = 0; h < 2; h++) {
                int a = m * 2 + h;
                #pragma unroll
                for (int j = 0; j < 8; j++) {
                    unsigned long long e2 =
                        pk2(ex2(cA[m][j][2 * h]), ex2(cA[m][j][2 * h + 1]));
                    den2[a] = ffma2(e2, one2,    den2[a]);
                    n02[a]  = ffma2(e2, col2[j], n02[a]);
                    n12[a]  = ffma2(e2, row2,    n12[a]);
                }
            }
    };

    // tile 0
    asm volatile("cp.async.wait_group 1;" ::: "memory");
    __syncthreads();
    prefetch(2);
    asm volatile("cp.async.commit_group;");
    do_mma(0);
    if (!late) epi(0);

    // tiles 1..31: even warps [MMA(t), epi(t)]; odd warps [epi(t-1), MMA(t)]
    for (int t = 1; t < 32; t++) {
        if (t < 31) asm volatile("cp.async.wait_group 1;" ::: "memory");
        else        asm volatile("cp.async.wait_group 0;" ::: "memory");
        __syncthreads();
        if (t + 2 < 32) {
            prefetch(t + 2);
            asm volatile("cp.async.commit_group;");
        }
        if (late) { epi(t - 1); do_mma(t); }
        else      { do_mma(t);  epi(t);    }
    }
    if (late) epi(31);

    // fold packed halves, reduce across the 4 lanes of each row group
    float* red = (float*)(smem + SM_RED);
    #pragma unroll
    for (int a = 0; a < 4; a++) {
        float dl, dh, al, ah2, bl, bh;
        upk2(dl, dh, den2[a]);
        upk2(al, ah2, n02[a]);
        upk2(bl, bh, n12[a]);
        float den = dl + dh, n0 = al + ah2, n1 = bl + bh;
        #pragma unroll
        for (int off = 1; off < 4; off <<= 1) {
            den += __shfl_xor_sync(0xffffffffu, den, off, 4);
            n0  += __shfl_xor_sync(0xffffffffu, n0,  off, 4);
            n1  += __shfl_xor_sync(0xffffffffu, n1,  off, 4);
        }
        if ((lane & 3) == 0) {
            int qrow = mq + (a >> 1) * 16 + (lane >> 2) + (a & 1) * 8;
            int base = (nw * 128 + qrow) * 3;
            red[base] = den; red[base + 1] = n0; red[base + 2] = n1;
        }
    }
    __syncthreads();

    if (tid < 128) {
        float d  = red[tid * 3]     + red[(128 + tid) * 3];
        float n0 = red[tid * 3 + 1] + red[(128 + tid) * 3 + 1];
        float n1 = red[tid * 3 + 2] + red[(128 + tid) * 3 + 2];
        float inv = 1.0f / (32.0f * d);   // (uv/64)*2 - 1
        float* o = out + ((size_t)bb * 4096 + q0 + tid) * 2;
        o[0] = n0 * inv - 1.0f;
        o[1] = n1 * inv - 1.0f;
    }
}

extern "C" void kernel_launch(void* const* d_in, const int* in_sizes, int n_in,
                              void* d_out, int out_size) {
    const float* x = (const float*)d_in[0];
    const float* y = (const float*)d_in[1];
    float* out = (float*)d_out;

    cudaFuncSetAttribute(uv_kernel,
                         cudaFuncAttributeMaxDynamicSharedMemorySize,
                         (int)SMEM_TOTAL);
    ytrans_kernel<<<1024, 256>>>(y);
    uv_kernel<<<128, 256, SMEM_TOTAL>>>(x, out);
}